// round 3
// baseline (speedup 1.0000x reference)
#include <cuda_runtime.h>
#include <cuda_bf16.h>
#include <math.h>

// Problem constants
#define BATCH 2
#define SEQ   2048
#define EMBED 1024
#define HEADS 16
#define HDIM  64
#define MTOT  (BATCH*SEQ)       // 4096 rows for projections

// Scratch (device globals; no allocation allowed)
__device__ float g_q[BATCH*HEADS*SEQ*HDIM];    // [B,H,S,Dh]
__device__ float g_k[BATCH*HEADS*SEQ*HDIM];
__device__ float g_v[BATCH*HEADS*SEQ*HDIM];
__device__ float g_attn[BATCH*SEQ*EMBED];      // [B,S,D]

// ---------------------------------------------------------------------------
// Tiled GEMM: C = A[M,K] @ W[N,K]^T + bias[N]
// Block tile 64x64, K-tile 32, 256 threads, 4x4 microtile per thread.
// SPLIT_HEADS: write C into [B,H,S,Dh] layout (for Q/K/V); else row-major [M,N].
// ---------------------------------------------------------------------------
template<bool SPLIT_HEADS>
__global__ __launch_bounds__(256)
void gemm_bias_kernel(const float* __restrict__ A,
                      const float* __restrict__ W,
                      const float* __restrict__ bias,
                      float* __restrict__ C,
                      int Kdim, int Ndim)
{
    __shared__ float As[32][65];
    __shared__ float Bs[32][65];

    const int t  = threadIdx.x;
    const int tx = t & 15;
    const int ty = t >> 4;
    const int m0 = blockIdx.y * 64;
    const int n0 = blockIdx.x * 64;

    float acc[4][4];
#pragma unroll
    for (int i = 0; i < 4; i++)
#pragma unroll
        for (int j = 0; j < 4; j++) acc[i][j] = 0.f;

    for (int k0 = 0; k0 < Kdim; k0 += 32) {
#pragma unroll
        for (int i = 0; i < 8; i++) {
            int e  = t + i * 256;           // 0..2047
            int mm = e >> 5;                // 0..63
            int kk = e & 31;                // 0..31
            As[kk][mm] = A[(size_t)(m0 + mm) * Kdim + k0 + kk];
            Bs[kk][mm] = W[(size_t)(n0 + mm) * Kdim + k0 + kk];
        }
        __syncthreads();
#pragma unroll
        for (int kk = 0; kk < 32; kk++) {
            float a[4], b[4];
#pragma unroll
            for (int i = 0; i < 4; i++) a[i] = As[kk][ty * 4 + i];
#pragma unroll
            for (int j = 0; j < 4; j++) b[j] = Bs[kk][tx * 4 + j];
#pragma unroll
            for (int i = 0; i < 4; i++)
#pragma unroll
                for (int j = 0; j < 4; j++) acc[i][j] += a[i] * b[j];
        }
        __syncthreads();
    }

#pragma unroll
    for (int i = 0; i < 4; i++) {
        int m = m0 + ty * 4 + i;
#pragma unroll
        for (int j = 0; j < 4; j++) {
            int n = n0 + tx * 4 + j;
            float val = acc[i][j] + bias[n];
            if (SPLIT_HEADS) {
                int b  = m >> 11;       // m / SEQ
                int s  = m & (SEQ - 1);
                int h  = n >> 6;        // n / HDIM
                int dh = n & (HDIM - 1);
                C[(((size_t)b * HEADS + h) * SEQ + s) * HDIM + dh] = val;
            } else {
                C[(size_t)m * Ndim + n] = val;
            }
        }
    }
}

// ---------------------------------------------------------------------------
// Flash attention, fp32. One block = 64 queries of one (b,h).
// 256 threads. KV tiles of 64. Online softmax.
// Dynamic smem: Qs, Kt (d-major), Vs, Ss -- each 64x65 floats.
// ---------------------------------------------------------------------------
#define TPAD 65
#define ATTN_SMEM (4 * 64 * TPAD * (int)sizeof(float))

__global__ __launch_bounds__(256)
void attn_kernel(const float* __restrict__ gq,
                 const float* __restrict__ gk,
                 const float* __restrict__ gv,
                 const int*   __restrict__ mask,
                 float* __restrict__ gattn)
{
    extern __shared__ float sm[];
    float* Qs = sm;                       // [64][65]  (q row, d)
    float* Kt = Qs + 64 * TPAD;           // [64][65]  (d, k)  transposed
    float* Vs = Kt + 64 * TPAD;           // [64][65]  (k, d)
    float* Ss = Vs + 64 * TPAD;           // [64][65]  (q, k)

    const int t   = threadIdx.x;
    const int bh  = blockIdx.y;           // 0..31
    const int q0  = blockIdx.x * 64;

    // Layout A (score GEMM): 16x16 thread grid, 4x4 microtile
    const int tx = t & 15;
    const int ty = t >> 4;
    // Layout B (softmax / PV): 4 threads per query row
    const int r = t >> 2;                 // 0..63
    const int p = t & 3;                  // 16-col chunk

    const size_t base = (size_t)bh * SEQ;

    // Load Q tile
#pragma unroll
    for (int i = 0; i < 16; i++) {
        int e  = t + i * 256;
        int rr = e >> 6, d = e & 63;
        Qs[rr * TPAD + d] = gq[(base + q0 + rr) * HDIM + d];
    }

    float m_run = -INFINITY, l_run = 0.f;
    float acc[16];
#pragma unroll
    for (int j = 0; j < 16; j++) acc[j] = 0.f;

    const float scale = 0.125f;           // 1/sqrt(64)

    for (int k0 = 0; k0 < SEQ; k0 += 64) {
        __syncthreads();  // previous PV phase done with Vs/Ss
        // Load K (transposed) and V tiles
#pragma unroll
        for (int i = 0; i < 16; i++) {
            int e  = t + i * 256;
            int kr = e >> 6, d = e & 63;
            float kvv = gk[(base + k0 + kr) * HDIM + d];
            Kt[d * TPAD + kr] = kvv;
            Vs[kr * TPAD + d] = gv[(base + k0 + kr) * HDIM + d];
        }
        __syncthreads();

        // S = Q @ K^T (4x4 per thread)
        float s4[4][4];
#pragma unroll
        for (int i = 0; i < 4; i++)
#pragma unroll
            for (int j = 0; j < 4; j++) s4[i][j] = 0.f;
        for (int d = 0; d < 64; d++) {
            float a[4], b[4];
#pragma unroll
            for (int i = 0; i < 4; i++) a[i] = Qs[(ty * 4 + i) * TPAD + d];
#pragma unroll
            for (int j = 0; j < 4; j++) b[j] = Kt[d * TPAD + tx * 4 + j];
#pragma unroll
            for (int i = 0; i < 4; i++)
#pragma unroll
                for (int j = 0; j < 4; j++) s4[i][j] += a[i] * b[j];
        }
        // scale + mask + store to Ss
#pragma unroll
        for (int i = 0; i < 4; i++) {
            int qq = q0 + ty * 4 + i;
#pragma unroll
            for (int j = 0; j < 4; j++) {
                int kk = k0 + tx * 4 + j;
                float sv = s4[i][j] * scale;
                if (mask[(size_t)qq * SEQ + kk] == 0) sv = -1e9f;
                Ss[(ty * 4 + i) * TPAD + tx * 4 + j] = sv;
            }
        }
        __syncthreads();

        // Online softmax (layout B): 4 lanes per row
        float mt = -INFINITY;
#pragma unroll
        for (int c = 0; c < 16; c++)
            mt = fmaxf(mt, Ss[r * TPAD + p * 16 + c]);
        mt = fmaxf(mt, __shfl_xor_sync(0xffffffffu, mt, 1));
        mt = fmaxf(mt, __shfl_xor_sync(0xffffffffu, mt, 2));
        float m_new = fmaxf(m_run, mt);
        float alpha = __expf(m_run - m_new);

        float lsum = 0.f;
#pragma unroll
        for (int c = 0; c < 16; c++) {
            float pv = __expf(Ss[r * TPAD + p * 16 + c] - m_new);
            Ss[r * TPAD + p * 16 + c] = pv;
            lsum += pv;
        }
        lsum += __shfl_xor_sync(0xffffffffu, lsum, 1);
        lsum += __shfl_xor_sync(0xffffffffu, lsum, 2);

        l_run = l_run * alpha + lsum;
        m_run = m_new;
#pragma unroll
        for (int j = 0; j < 16; j++) acc[j] *= alpha;
        __syncthreads();  // all P written

        // O += P @ V  (each thread: row r, cols p*16..p*16+15)
        for (int k = 0; k < 64; k++) {
            float pv = Ss[r * TPAD + k];
#pragma unroll
            for (int j = 0; j < 16; j++)
                acc[j] += pv * Vs[k * TPAD + p * 16 + j];
        }
    }

    // Write out: [B,S,D] with D index = h*64 + dh
    const int b = bh / HEADS, h = bh % HEADS;
    const float inv = 1.f / l_run;
    const size_t orow = ((size_t)b * SEQ + q0 + r) * EMBED + h * HDIM + p * 16;
#pragma unroll
    for (int j = 0; j < 16; j++)
        gattn[orow + j] = acc[j] * inv;
}

// ---------------------------------------------------------------------------
extern "C" void kernel_launch(void* const* d_in, const int* in_sizes, int n_in,
                              void* d_out, int out_size)
{
    const float* hidden = (const float*)d_in[0];
    const int*   mask   = (const int*)  d_in[1];
    const float* Wq     = (const float*)d_in[2];
    const float* bq     = (const float*)d_in[3];
    const float* Wk     = (const float*)d_in[4];
    const float* bk     = (const float*)d_in[5];
    const float* Wv     = (const float*)d_in[6];
    const float* bv     = (const float*)d_in[7];
    const float* Wo     = (const float*)d_in[8];
    const float* bo     = (const float*)d_in[9];
    float* out = (float*)d_out;

    float *q, *k, *v, *attn;
    cudaGetSymbolAddress((void**)&q,    g_q);
    cudaGetSymbolAddress((void**)&k,    g_k);
    cudaGetSymbolAddress((void**)&v,    g_v);
    cudaGetSymbolAddress((void**)&attn, g_attn);

    static bool attr_set = false;
    if (!attr_set) {
        cudaFuncSetAttribute(attn_kernel,
                             cudaFuncAttributeMaxDynamicSharedMemorySize,
                             ATTN_SMEM);
        attr_set = true;
    }

    dim3 gblk(256);
    dim3 ggrid(EMBED / 64, MTOT / 64);   // (16, 64)

    // QKV projections -> [B,H,S,Dh]
    gemm_bias_kernel<true><<<ggrid, gblk>>>(hidden, Wq, bq, q, EMBED, EMBED);
    gemm_bias_kernel<true><<<ggrid, gblk>>>(hidden, Wk, bk, k, EMBED, EMBED);
    gemm_bias_kernel<true><<<ggrid, gblk>>>(hidden, Wv, bv, v, EMBED, EMBED);

    // Attention
    dim3 agrid(SEQ / 64, BATCH * HEADS); // (32, 32)
    attn_kernel<<<agrid, 256, ATTN_SMEM>>>(q, k, v, mask, attn);

    // Output projection -> [B,S,D] directly into d_out
    gemm_bias_kernel<false><<<ggrid, gblk>>>(attn, Wo, bo, out, EMBED, EMBED);
}

// round 5
// speedup vs baseline: 3.7464x; 3.7464x over previous
#include <cuda_runtime.h>
#include <cuda_bf16.h>
#include <math.h>
#include <stdint.h>

// Problem constants
#define BATCH 2
#define SEQ   2048
#define EMBED 1024
#define HEADS 16
#define HDIM  64
#define MTOT  (BATCH*SEQ)     // 4096
#define BH    (BATCH*HEADS)   // 32

// ---------------------------------------------------------------------------
// Scratch (device globals; no allocation allowed)
// hi/lo bf16 splits of everything (bf16x3 precision scheme)
// ---------------------------------------------------------------------------
__device__ __nv_bfloat16 g_hh[MTOT*EMBED],  g_hl[MTOT*EMBED];     // hidden
__device__ __nv_bfloat16 g_wqh[EMBED*EMBED], g_wql[EMBED*EMBED];
__device__ __nv_bfloat16 g_wkh[EMBED*EMBED], g_wkl[EMBED*EMBED];
__device__ __nv_bfloat16 g_wvh[EMBED*EMBED], g_wvl[EMBED*EMBED];
__device__ __nv_bfloat16 g_woh[EMBED*EMBED], g_wol[EMBED*EMBED];
__device__ __nv_bfloat16 g_qh[BH*SEQ*HDIM],  g_ql[BH*SEQ*HDIM];   // [bh][s][dh]
__device__ __nv_bfloat16 g_kh[BH*SEQ*HDIM],  g_kl[BH*SEQ*HDIM];   // [bh][s][dh]
__device__ __nv_bfloat16 g_vth[BH*SEQ*HDIM], g_vtl[BH*SEQ*HDIM];  // [bh][dh][s] (transposed)
__device__ __nv_bfloat16 g_ah[MTOT*EMBED],   g_al[MTOT*EMBED];    // attn out [b*s][d]

// ---------------------------------------------------------------------------
// Helpers
// ---------------------------------------------------------------------------
__device__ __forceinline__ uint32_t pack_bf2(float lo_elem, float hi_elem) {
    // result: low half = bf16(lo_elem), high half = bf16(hi_elem)
    uint32_t r;
    asm("cvt.rn.bf16x2.f32 %0, %1, %2;" : "=r"(r) : "f"(hi_elem), "f"(lo_elem));
    return r;
}

__device__ __forceinline__ void split_pack2(float x, float y, uint32_t& hi, uint32_t& lo) {
    float xh = __bfloat162float(__float2bfloat16_rn(x));
    float yh = __bfloat162float(__float2bfloat16_rn(y));
    hi = pack_bf2(xh, yh);
    lo = pack_bf2(x - xh, y - yh);
}

__device__ __forceinline__ void mma16816(float* c, const uint32_t* a, const uint32_t* b) {
    asm volatile(
        "mma.sync.aligned.m16n8k16.row.col.f32.bf16.bf16.f32 "
        "{%0,%1,%2,%3}, {%4,%5,%6,%7}, {%8,%9}, {%0,%1,%2,%3};"
        : "+f"(c[0]), "+f"(c[1]), "+f"(c[2]), "+f"(c[3])
        : "r"(a[0]), "r"(a[1]), "r"(a[2]), "r"(a[3]), "r"(b[0]), "r"(b[1]));
}

// ---------------------------------------------------------------------------
// fp32 -> (hi, lo) bf16 split
// ---------------------------------------------------------------------------
__global__ __launch_bounds__(256)
void split_kernel(const float* __restrict__ x,
                  __nv_bfloat16* __restrict__ h,
                  __nv_bfloat16* __restrict__ l, int n)
{
    int i = (blockIdx.x * 256 + threadIdx.x) * 4;
    if (i >= n) return;
    float4 v = *(const float4*)(x + i);
    float a[4] = {v.x, v.y, v.z, v.w};
#pragma unroll
    for (int j = 0; j < 4; j++) {
        __nv_bfloat16 hv = __float2bfloat16_rn(a[j]);
        h[i + j] = hv;
        l[i + j] = __float2bfloat16_rn(a[j] - __bfloat162float(hv));
    }
}

// ---------------------------------------------------------------------------
// bf16x3 GEMM: C[M,N] = A[M,K] @ W[N,K]^T + bias, M=4096, N=K=1024.
// Block 128x128, 8 warps (2m x 4n), warp tile 64x32, k-tile 32.
// MODE 0: fp32 out row-major.
// MODE 1: hi/lo bf16 out, head-split [bh][s][dh]   (Q, K)
// MODE 2: hi/lo bf16 out, head-split transposed [bh][dh][s]  (V)
// ---------------------------------------------------------------------------
#define KT 32
#define SSTR 40   // smem row stride in halves (80B, 16B aligned, conflict-light)

template<int MODE>
__global__ __launch_bounds__(256, 1)
void mma_gemm(const __nv_bfloat16* __restrict__ Ah, const __nv_bfloat16* __restrict__ Al,
              const __nv_bfloat16* __restrict__ Bh, const __nv_bfloat16* __restrict__ Bl,
              const float* __restrict__ bias,
              float* __restrict__ outF,
              __nv_bfloat16* __restrict__ outH, __nv_bfloat16* __restrict__ outL)
{
    const int K = EMBED;
    __shared__ __nv_bfloat16 sAh[128*SSTR], sAl[128*SSTR];
    __shared__ __nv_bfloat16 sBh[128*SSTR], sBl[128*SSTR];

    const int t = threadIdx.x, lane = t & 31, w = t >> 5;
    const int g = lane >> 2, tg = lane & 3;
    const int wm = w >> 2, wn = w & 3;             // wm 0..1, wn 0..3
    const int m0 = blockIdx.y * 128, n0 = blockIdx.x * 128;

    float acc[4][4][4];
#pragma unroll
    for (int a = 0; a < 4; a++)
#pragma unroll
        for (int b = 0; b < 4; b++)
#pragma unroll
            for (int c = 0; c < 4; c++) acc[a][b][c] = 0.f;

    const int lr = t >> 1;            // 0..127
    const int lc = (t & 1) * 16;      // half col 0 / 16
    const __nv_bfloat16* pAh = Ah + (size_t)(m0 + lr) * K + lc;
    const __nv_bfloat16* pAl = Al + (size_t)(m0 + lr) * K + lc;
    const __nv_bfloat16* pBh = Bh + (size_t)(n0 + lr) * K + lc;
    const __nv_bfloat16* pBl = Bl + (size_t)(n0 + lr) * K + lc;
    __nv_bfloat16* qAh = &sAh[lr*SSTR + lc];
    __nv_bfloat16* qAl = &sAl[lr*SSTR + lc];
    __nv_bfloat16* qBh = &sBh[lr*SSTR + lc];
    __nv_bfloat16* qBl = &sBl[lr*SSTR + lc];

    for (int k0 = 0; k0 < K; k0 += KT) {
        __syncthreads();
        *(uint4*)qAh       = *(const uint4*)(pAh + k0);
        *(uint4*)(qAh + 8) = *(const uint4*)(pAh + k0 + 8);
        *(uint4*)qAl       = *(const uint4*)(pAl + k0);
        *(uint4*)(qAl + 8) = *(const uint4*)(pAl + k0 + 8);
        *(uint4*)qBh       = *(const uint4*)(pBh + k0);
        *(uint4*)(qBh + 8) = *(const uint4*)(pBh + k0 + 8);
        *(uint4*)qBl       = *(const uint4*)(pBl + k0);
        *(uint4*)(qBl + 8) = *(const uint4*)(pBl + k0 + 8);
        __syncthreads();

#pragma unroll
        for (int ks = 0; ks < 2; ks++) {
            const int kb = ks * 16;
            uint32_t aH[4][4], aL[4][4];
#pragma unroll
            for (int mf = 0; mf < 4; mf++) {
                int r = wm * 64 + mf * 16 + g;
                int i0 = r * SSTR + kb + 2 * tg;
                int i1 = (r + 8) * SSTR + kb + 2 * tg;
                aH[mf][0] = *(const uint32_t*)&sAh[i0];
                aH[mf][1] = *(const uint32_t*)&sAh[i1];
                aH[mf][2] = *(const uint32_t*)&sAh[i0 + 8];
                aH[mf][3] = *(const uint32_t*)&sAh[i1 + 8];
                aL[mf][0] = *(const uint32_t*)&sAl[i0];
                aL[mf][1] = *(const uint32_t*)&sAl[i1];
                aL[mf][2] = *(const uint32_t*)&sAl[i0 + 8];
                aL[mf][3] = *(const uint32_t*)&sAl[i1 + 8];
            }
            uint32_t bH[4][2], bL[4][2];
#pragma unroll
            for (int nf = 0; nf < 4; nf++) {
                int c = wn * 32 + nf * 8 + g;
                int i0 = c * SSTR + kb + 2 * tg;
                bH[nf][0] = *(const uint32_t*)&sBh[i0];
                bH[nf][1] = *(const uint32_t*)&sBh[i0 + 8];
                bL[nf][0] = *(const uint32_t*)&sBl[i0];
                bL[nf][1] = *(const uint32_t*)&sBl[i0 + 8];
            }
#pragma unroll
            for (int mf = 0; mf < 4; mf++)
#pragma unroll
                for (int nf = 0; nf < 4; nf++) {
                    mma16816(acc[mf][nf], aH[mf], bH[nf]);
                    mma16816(acc[mf][nf], aH[mf], bL[nf]);
                    mma16816(acc[mf][nf], aL[mf], bH[nf]);
                }
        }
    }

    // Epilogue
#pragma unroll
    for (int mf = 0; mf < 4; mf++)
#pragma unroll
        for (int nf = 0; nf < 4; nf++) {
            int r0 = m0 + wm * 64 + mf * 16 + g;
            int c0 = n0 + wn * 32 + nf * 8 + 2 * tg;
#pragma unroll
            for (int e = 0; e < 4; e++) {
                int r = r0 + ((e >= 2) ? 8 : 0);
                int c = c0 + (e & 1);
                float val = acc[mf][nf][e] + bias[c];
                if (MODE == 0) {
                    outF[(size_t)r * EMBED + c] = val;
                } else {
                    int b  = r >> 11;
                    int s  = r & (SEQ - 1);
                    int h  = c >> 6;
                    int dh = c & (HDIM - 1);
                    size_t idx;
                    if (MODE == 1)
                        idx = (((size_t)(b * HEADS + h)) * SEQ + s) * HDIM + dh;
                    else
                        idx = (((size_t)(b * HEADS + h)) * HDIM + dh) * SEQ + s;
                    __nv_bfloat16 hv = __float2bfloat16_rn(val);
                    outH[idx] = hv;
                    outL[idx] = __float2bfloat16_rn(val - __bfloat162float(hv));
                }
            }
        }
}

// ---------------------------------------------------------------------------
// Flash attention on HMMA fragments, bf16x3.
// Block = 128 queries of one (b,h). 8 warps, warp owns 16 q-rows x full tiles.
// KV tile = 64 keys. Softmax done in accumulator fragments; P repacked
// in-register into A-fragments for PV (no smem round-trip).
// ---------------------------------------------------------------------------
#define KSTR 72  // smem row stride in halves (144B, 16B aligned, conflict-free frags)

__global__ __launch_bounds__(256, 1)
void attn_mma(const __nv_bfloat16* __restrict__ qh_, const __nv_bfloat16* __restrict__ ql_,
              const __nv_bfloat16* __restrict__ kh_, const __nv_bfloat16* __restrict__ kl_,
              const __nv_bfloat16* __restrict__ vth_, const __nv_bfloat16* __restrict__ vtl_,
              const int* __restrict__ mask,
              __nv_bfloat16* __restrict__ aH, __nv_bfloat16* __restrict__ aL)
{
    __shared__ __nv_bfloat16 sKh[64*KSTR], sKl[64*KSTR];
    __shared__ __nv_bfloat16 sVh[64*KSTR], sVl[64*KSTR];

    const int t = threadIdx.x, lane = t & 31, w = t >> 5;
    const int g = lane >> 2, tg = lane & 3;
    const int bh = blockIdx.y;
    const int q0 = blockIdx.x * 128;
    const size_t base = (size_t)bh * SEQ * HDIM;

    // Q fragments (registers, loaded once): 4 d-ksteps x 4 regs, hi+lo
    const int r0 = q0 + w * 16 + g;   // this thread's first q row (global s index)
    uint32_t qfh[4][4], qfl[4][4];
#pragma unroll
    for (int kf = 0; kf < 4; kf++) {
        size_t i0 = base + (size_t)r0 * HDIM + kf * 16 + 2 * tg;
        size_t i1 = base + (size_t)(r0 + 8) * HDIM + kf * 16 + 2 * tg;
        qfh[kf][0] = *(const uint32_t*)&qh_[i0];
        qfh[kf][1] = *(const uint32_t*)&qh_[i1];
        qfh[kf][2] = *(const uint32_t*)&qh_[i0 + 8];
        qfh[kf][3] = *(const uint32_t*)&qh_[i1 + 8];
        qfl[kf][0] = *(const uint32_t*)&ql_[i0];
        qfl[kf][1] = *(const uint32_t*)&ql_[i1];
        qfl[kf][2] = *(const uint32_t*)&ql_[i0 + 8];
        qfl[kf][3] = *(const uint32_t*)&ql_[i1 + 8];
    }

    float o[8][4];
#pragma unroll
    for (int nf = 0; nf < 8; nf++)
#pragma unroll
        for (int e = 0; e < 4; e++) o[nf][e] = 0.f;
    float m1 = -INFINITY, m2 = -INFINITY, l1 = 0.f, l2 = 0.f;

    // tile staging: 64 rows x 64 halves per array; 4 threads/row, 16 halves each
    const int lr  = t >> 2;
    const int lcb = (t & 3) * 16;
    const __nv_bfloat16* pKh = kh_  + base + (size_t)lr * HDIM + lcb;
    const __nv_bfloat16* pKl = kl_  + base + (size_t)lr * HDIM + lcb;
    const __nv_bfloat16* pVh = vth_ + base + (size_t)lr * SEQ  + lcb;
    const __nv_bfloat16* pVl = vtl_ + base + (size_t)lr * SEQ  + lcb;
    __nv_bfloat16* qKh = &sKh[lr*KSTR + lcb];
    __nv_bfloat16* qKl = &sKl[lr*KSTR + lcb];
    __nv_bfloat16* qVh = &sVh[lr*KSTR + lcb];
    __nv_bfloat16* qVl = &sVl[lr*KSTR + lcb];

    const float scale = 0.125f;  // 1/sqrt(64)

    for (int k0 = 0; k0 < SEQ; k0 += 64) {
        __syncthreads();
        *(uint4*)qKh       = *(const uint4*)(pKh + (size_t)k0 * HDIM);
        *(uint4*)(qKh + 8) = *(const uint4*)(pKh + (size_t)k0 * HDIM + 8);
        *(uint4*)qKl       = *(const uint4*)(pKl + (size_t)k0 * HDIM);
        *(uint4*)(qKl + 8) = *(const uint4*)(pKl + (size_t)k0 * HDIM + 8);
        *(uint4*)qVh       = *(const uint4*)(pVh + k0);
        *(uint4*)(qVh + 8) = *(const uint4*)(pVh + k0 + 8);
        *(uint4*)qVl       = *(const uint4*)(pVl + k0);
        *(uint4*)(qVl + 8) = *(const uint4*)(pVl + k0 + 8);
        __syncthreads();

        // ----- S = Q @ K^T (bf16x3) -----
        float s[8][4];
#pragma unroll
        for (int nf = 0; nf < 8; nf++)
#pragma unroll
            for (int e = 0; e < 4; e++) s[nf][e] = 0.f;

#pragma unroll
        for (int kf = 0; kf < 4; kf++) {
            const int kb = kf * 16;
#pragma unroll
            for (int nf = 0; nf < 8; nf++) {
                int c = nf * 8 + g;
                int idx = c * KSTR + kb + 2 * tg;
                uint32_t bh2[2] = { *(const uint32_t*)&sKh[idx], *(const uint32_t*)&sKh[idx + 8] };
                uint32_t bl2[2] = { *(const uint32_t*)&sKl[idx], *(const uint32_t*)&sKl[idx + 8] };
                mma16816(s[nf], qfh[kf], bh2);
                mma16816(s[nf], qfh[kf], bl2);
                mma16816(s[nf], qfl[kf], bh2);
            }
        }

        // ----- scale + mask -----
#pragma unroll
        for (int nf = 0; nf < 8; nf++) {
            int kc = k0 + nf * 8 + 2 * tg;
            int2 mv0 = *(const int2*)&mask[(size_t)r0 * SEQ + kc];
            int2 mv1 = *(const int2*)&mask[(size_t)(r0 + 8) * SEQ + kc];
            s[nf][0] = mv0.x ? s[nf][0] * scale : -1e9f;
            s[nf][1] = mv0.y ? s[nf][1] * scale : -1e9f;
            s[nf][2] = mv1.x ? s[nf][2] * scale : -1e9f;
            s[nf][3] = mv1.y ? s[nf][3] * scale : -1e9f;
        }

        // ----- online softmax (rows g and g+8; cols spread over nf x quad) -----
        float mt1 = -INFINITY, mt2 = -INFINITY;
#pragma unroll
        for (int nf = 0; nf < 8; nf++) {
            mt1 = fmaxf(mt1, fmaxf(s[nf][0], s[nf][1]));
            mt2 = fmaxf(mt2, fmaxf(s[nf][2], s[nf][3]));
        }
        mt1 = fmaxf(mt1, __shfl_xor_sync(0xffffffffu, mt1, 1));
        mt1 = fmaxf(mt1, __shfl_xor_sync(0xffffffffu, mt1, 2));
        mt2 = fmaxf(mt2, __shfl_xor_sync(0xffffffffu, mt2, 1));
        mt2 = fmaxf(mt2, __shfl_xor_sync(0xffffffffu, mt2, 2));
        float m1n = fmaxf(m1, mt1), m2n = fmaxf(m2, mt2);
        float a1 = __expf(m1 - m1n), a2 = __expf(m2 - m2n);

        float sum1 = 0.f, sum2 = 0.f;
#pragma unroll
        for (int nf = 0; nf < 8; nf++) {
            s[nf][0] = __expf(s[nf][0] - m1n);
            s[nf][1] = __expf(s[nf][1] - m1n);
            s[nf][2] = __expf(s[nf][2] - m2n);
            s[nf][3] = __expf(s[nf][3] - m2n);
            sum1 += s[nf][0] + s[nf][1];
            sum2 += s[nf][2] + s[nf][3];
        }
        sum1 += __shfl_xor_sync(0xffffffffu, sum1, 1);
        sum1 += __shfl_xor_sync(0xffffffffu, sum1, 2);
        sum2 += __shfl_xor_sync(0xffffffffu, sum2, 1);
        sum2 += __shfl_xor_sync(0xffffffffu, sum2, 2);
        l1 = l1 * a1 + sum1;
        l2 = l2 * a2 + sum2;
        m1 = m1n; m2 = m2n;

#pragma unroll
        for (int nf = 0; nf < 8; nf++) {
            o[nf][0] *= a1; o[nf][1] *= a1;
            o[nf][2] *= a2; o[nf][3] *= a2;
        }

        // ----- O += P @ V (P in-register -> A frags; V^T tiles as B) -----
#pragma unroll
        for (int kf = 0; kf < 4; kf++) {
            uint32_t pH[4], pL[4];
            split_pack2(s[2*kf][0],   s[2*kf][1],   pH[0], pL[0]);
            split_pack2(s[2*kf][2],   s[2*kf][3],   pH[1], pL[1]);
            split_pack2(s[2*kf+1][0], s[2*kf+1][1], pH[2], pL[2]);
            split_pack2(s[2*kf+1][2], s[2*kf+1][3], pH[3], pL[3]);
            const int kb = kf * 16;
#pragma unroll
            for (int nf = 0; nf < 8; nf++) {
                int c = nf * 8 + g;
                int idx = c * KSTR + kb + 2 * tg;
                uint32_t bh2[2] = { *(const uint32_t*)&sVh[idx], *(const uint32_t*)&sVh[idx + 8] };
                uint32_t bl2[2] = { *(const uint32_t*)&sVl[idx], *(const uint32_t*)&sVl[idx + 8] };
                mma16816(o[nf], pH, bh2);
                mma16816(o[nf], pH, bl2);
                mma16816(o[nf], pL, bh2);
            }
        }
    }

    // ----- epilogue: attn [b][s][D] hi/lo bf16 -----
    const float inv1 = 1.f / l1, inv2 = 1.f / l2;
    const int b = bh / HEADS, h = bh % HEADS;
#pragma unroll
    for (int nf = 0; nf < 8; nf++) {
        int col = h * HDIM + nf * 8 + 2 * tg;
        size_t i0 = ((size_t)(b * SEQ + r0)) * EMBED + col;
        size_t i1 = ((size_t)(b * SEQ + r0 + 8)) * EMBED + col;
        float v00 = o[nf][0] * inv1, v01 = o[nf][1] * inv1;
        float v10 = o[nf][2] * inv2, v11 = o[nf][3] * inv2;
        __nv_bfloat16 hv;
        hv = __float2bfloat16_rn(v00); aH[i0]   = hv; aL[i0]   = __float2bfloat16_rn(v00 - __bfloat162float(hv));
        hv = __float2bfloat16_rn(v01); aH[i0+1] = hv; aL[i0+1] = __float2bfloat16_rn(v01 - __bfloat162float(hv));
        hv = __float2bfloat16_rn(v10); aH[i1]   = hv; aL[i1]   = __float2bfloat16_rn(v10 - __bfloat162float(hv));
        hv = __float2bfloat16_rn(v11); aH[i1+1] = hv; aL[i1+1] = __float2bfloat16_rn(v11 - __bfloat162float(hv));
    }
}

// ---------------------------------------------------------------------------
extern "C" void kernel_launch(void* const* d_in, const int* in_sizes, int n_in,
                              void* d_out, int out_size)
{
    const float* hidden = (const float*)d_in[0];
    const int*   mask   = (const int*)  d_in[1];
    const float* Wq     = (const float*)d_in[2];
    const float* bq     = (const float*)d_in[3];
    const float* Wk     = (const float*)d_in[4];
    const float* bk     = (const float*)d_in[5];
    const float* Wv     = (const float*)d_in[6];
    const float* bv     = (const float*)d_in[7];
    const float* Wo     = (const float*)d_in[8];
    const float* bo     = (const float*)d_in[9];
    float* out = (float*)d_out;

    __nv_bfloat16 *hh, *hl, *wqh, *wql, *wkh, *wkl, *wvh, *wvl, *woh, *wol;
    __nv_bfloat16 *qh, *ql, *kh, *kl, *vth, *vtl, *ah, *al;
    cudaGetSymbolAddress((void**)&hh,  g_hh);  cudaGetSymbolAddress((void**)&hl,  g_hl);
    cudaGetSymbolAddress((void**)&wqh, g_wqh); cudaGetSymbolAddress((void**)&wql, g_wql);
    cudaGetSymbolAddress((void**)&wkh, g_wkh); cudaGetSymbolAddress((void**)&wkl, g_wkl);
    cudaGetSymbolAddress((void**)&wvh, g_wvh); cudaGetSymbolAddress((void**)&wvl, g_wvl);
    cudaGetSymbolAddress((void**)&woh, g_woh); cudaGetSymbolAddress((void**)&wol, g_wol);
    cudaGetSymbolAddress((void**)&qh,  g_qh);  cudaGetSymbolAddress((void**)&ql,  g_ql);
    cudaGetSymbolAddress((void**)&kh,  g_kh);  cudaGetSymbolAddress((void**)&kl,  g_kl);
    cudaGetSymbolAddress((void**)&vth, g_vth); cudaGetSymbolAddress((void**)&vtl, g_vtl);
    cudaGetSymbolAddress((void**)&ah,  g_ah);  cudaGetSymbolAddress((void**)&al,  g_al);

    // Splits
    const int nH = MTOT * EMBED, nW = EMBED * EMBED;
    split_kernel<<<(nH/4 + 255)/256, 256>>>(hidden, hh, hl, nH);
    split_kernel<<<(nW/4 + 255)/256, 256>>>(Wq, wqh, wql, nW);
    split_kernel<<<(nW/4 + 255)/256, 256>>>(Wk, wkh, wkl, nW);
    split_kernel<<<(nW/4 + 255)/256, 256>>>(Wv, wvh, wvl, nW);
    split_kernel<<<(nW/4 + 255)/256, 256>>>(Wo, woh, wol, nW);

    // Projections (bf16x3 HMMA)
    dim3 gg(EMBED / 128, MTOT / 128);   // (8, 32)
    mma_gemm<1><<<gg, 256>>>(hh, hl, wqh, wql, bq, nullptr, qh, ql);
    mma_gemm<1><<<gg, 256>>>(hh, hl, wkh, wkl, bk, nullptr, kh, kl);
    mma_gemm<2><<<gg, 256>>>(hh, hl, wvh, wvl, bv, nullptr, vth, vtl);

    // Attention
    dim3 ag(SEQ / 128, BH);             // (16, 32)
    attn_mma<<<ag, 256>>>(qh, ql, kh, kl, vth, vtl, mask, ah, al);

    // Output projection -> fp32 d_out
    mma_gemm<0><<<gg, 256>>>(ah, al, woh, wol, bo, out, nullptr, nullptr);
}

// round 7
// speedup vs baseline: 4.8372x; 1.2912x over previous
#include <cuda_runtime.h>
#include <cuda_bf16.h>
#include <math.h>
#include <stdint.h>

// Problem constants
#define BATCH 2
#define SEQ   2048
#define EMBED 1024
#define HEADS 16
#define HDIM  64
#define MTOT  (BATCH*SEQ)     // 4096
#define BH    (BATCH*HEADS)   // 32

// ---------------------------------------------------------------------------
// Scratch (device globals; no allocation allowed)
// ---------------------------------------------------------------------------
__device__ __nv_bfloat16 g_hh[MTOT*EMBED],  g_hl[MTOT*EMBED];
__device__ __nv_bfloat16 g_wqh[EMBED*EMBED], g_wql[EMBED*EMBED];
__device__ __nv_bfloat16 g_wkh[EMBED*EMBED], g_wkl[EMBED*EMBED];
__device__ __nv_bfloat16 g_wvh[EMBED*EMBED], g_wvl[EMBED*EMBED];
__device__ __nv_bfloat16 g_woh[EMBED*EMBED], g_wol[EMBED*EMBED];
__device__ __nv_bfloat16 g_qh[BH*SEQ*HDIM],  g_ql[BH*SEQ*HDIM];   // [bh][s][dh]
__device__ __nv_bfloat16 g_kh[BH*SEQ*HDIM],  g_kl[BH*SEQ*HDIM];   // [bh][s][dh]
__device__ __nv_bfloat16 g_vth[BH*SEQ*HDIM], g_vtl[BH*SEQ*HDIM];  // [bh][dh][s]
__device__ __nv_bfloat16 g_ah[MTOT*EMBED],   g_al[MTOT*EMBED];    // attn out
__device__ int g_mflag[(SEQ/128)*(SEQ/64)];                        // [16][32]

// ---------------------------------------------------------------------------
// Helpers
// ---------------------------------------------------------------------------
__device__ __forceinline__ uint32_t pack_bf2(float lo_elem, float hi_elem) {
    uint32_t r;
    asm("cvt.rn.bf16x2.f32 %0, %1, %2;" : "=r"(r) : "f"(hi_elem), "f"(lo_elem));
    return r;
}
__device__ __forceinline__ void split_pack2(float x, float y, uint32_t& hi, uint32_t& lo) {
    float xh = __bfloat162float(__float2bfloat16_rn(x));
    float yh = __bfloat162float(__float2bfloat16_rn(y));
    hi = pack_bf2(xh, yh);
    lo = pack_bf2(x - xh, y - yh);
}
__device__ __forceinline__ void mma16816(float* c, const uint32_t* a, const uint32_t* b) {
    asm volatile(
        "mma.sync.aligned.m16n8k16.row.col.f32.bf16.bf16.f32 "
        "{%0,%1,%2,%3}, {%4,%5,%6,%7}, {%8,%9}, {%0,%1,%2,%3};"
        : "+f"(c[0]), "+f"(c[1]), "+f"(c[2]), "+f"(c[3])
        : "r"(a[0]), "r"(a[1]), "r"(a[2]), "r"(a[3]), "r"(b[0]), "r"(b[1]));
}
__device__ __forceinline__ uint32_t s2u(const void* p) {
    return (uint32_t)__cvta_generic_to_shared(p);
}
__device__ __forceinline__ void cpa16(uint32_t s, const void* g) {
    asm volatile("cp.async.cg.shared.global [%0], [%1], 16;" :: "r"(s), "l"(g));
}
__device__ __forceinline__ void cp_commit() { asm volatile("cp.async.commit_group;"); }
__device__ __forceinline__ void cp_wait1() { asm volatile("cp.async.wait_group 1;"); }
__device__ __forceinline__ void cp_wait0() { asm volatile("cp.async.wait_group 0;"); }
__device__ __forceinline__ void ldsm4(uint32_t* r, uint32_t a) {
    asm volatile("ldmatrix.sync.aligned.m8n8.x4.shared.b16 {%0,%1,%2,%3}, [%4];"
        : "=r"(r[0]), "=r"(r[1]), "=r"(r[2]), "=r"(r[3]) : "r"(a));
}

// ---------------------------------------------------------------------------
// fp32 -> (hi, lo) bf16 split; 8 elems/thread, vector stores
// ---------------------------------------------------------------------------
__global__ __launch_bounds__(256)
void split_kernel(const float* __restrict__ x,
                  __nv_bfloat16* __restrict__ h,
                  __nv_bfloat16* __restrict__ l, int n)
{
    int i = (blockIdx.x * 256 + threadIdx.x) * 8;
    if (i >= n) return;
    float4 v0 = *(const float4*)(x + i);
    float4 v1 = *(const float4*)(x + i + 4);
    float a[8] = {v0.x, v0.y, v0.z, v0.w, v1.x, v1.y, v1.z, v1.w};
    uint32_t hp[4], lp[4];
#pragma unroll
    for (int j = 0; j < 4; j++) split_pack2(a[2*j], a[2*j+1], hp[j], lp[j]);
    *(uint4*)(h + i) = make_uint4(hp[0], hp[1], hp[2], hp[3]);
    *(uint4*)(l + i) = make_uint4(lp[0], lp[1], lp[2], lp[3]);
}

// ---------------------------------------------------------------------------
// Mask block flags: flag[qb][kb] = any zero in mask[qb*128.., kb*64..]
// ---------------------------------------------------------------------------
__global__ __launch_bounds__(256)
void mask_flags_kernel(const int* __restrict__ mask)
{
    const int* p = mask + (size_t)(blockIdx.y * 128) * SEQ + blockIdx.x * 64;
    int local = 0;
    for (int i = threadIdx.x; i < 128 * 16; i += 256) {
        int r = i >> 4, c4 = i & 15;
        int4 v = ((const int4*)(p + (size_t)r * SEQ))[c4];
        if (v.x == 0 || v.y == 0 || v.z == 0 || v.w == 0) local = 1;
    }
    int any = __syncthreads_or(local);
    if (threadIdx.x == 0) g_mflag[blockIdx.y * (SEQ/64) + blockIdx.x] = any;
}

// ---------------------------------------------------------------------------
// bf16x3 GEMM: C[M,N] = A[M,K] @ W[N,K]^T + bias. Block 128x128, kt 32.
// cp.async double-buffered, ldmatrix-fed.
// MODE 0: fp32 row-major. MODE 1: hi/lo [bh][s][dh]. MODE 2: hi/lo [bh][dh][s].
// ---------------------------------------------------------------------------
#define KT    32
#define SSTR  40                      // halves; 80B row stride (conflict-free LDSM)
#define GARR  (128*SSTR*2)            // 10240 B per array
#define GSTAGE (4*GARR)               // 40960 B
#define GSMEM  (2*GSTAGE)             // 81920 B

template<int MODE>
__global__ __launch_bounds__(256)
void mma_gemm(const __nv_bfloat16* __restrict__ Ah, const __nv_bfloat16* __restrict__ Al,
              const __nv_bfloat16* __restrict__ Bh, const __nv_bfloat16* __restrict__ Bl,
              const float* __restrict__ bias,
              float* __restrict__ outF,
              __nv_bfloat16* __restrict__ outH, __nv_bfloat16* __restrict__ outL)
{
    extern __shared__ __nv_bfloat16 dsm[];
    const uint32_t sb = s2u(dsm);
    const int K = EMBED;
    const int t = threadIdx.x, lane = t & 31, w = t >> 5;
    const int g = lane >> 2, tg = lane & 3;
    const int wm = w >> 2, wn = w & 3;
    const int m0 = blockIdx.y * 128, n0 = blockIdx.x * 128;

    const int lr = t >> 1, lc = (t & 1) * 16;
    const __nv_bfloat16* gp[4] = {
        Ah + (size_t)(m0 + lr) * K + lc,
        Al + (size_t)(m0 + lr) * K + lc,
        Bh + (size_t)(n0 + lr) * K + lc,
        Bl + (size_t)(n0 + lr) * K + lc };
    const uint32_t sp = sb + (lr * SSTR + lc) * 2;

    const uint32_t aoff = sb + ((wm * 64 + (lane & 15)) * SSTR + (lane >> 4) * 8) * 2;
    const uint32_t boff = sb + 2 * GARR +
        (((wn * 32 + (lane & 7) + (lane >> 4) * 8) * SSTR + ((lane >> 3) & 1) * 8) * 2);

    float acc[4][4][4];
#pragma unroll
    for (int a = 0; a < 4; a++)
#pragma unroll
        for (int b = 0; b < 4; b++)
#pragma unroll
            for (int c = 0; c < 4; c++) acc[a][b][c] = 0.f;

    // prologue
    {
#pragma unroll
        for (int a = 0; a < 4; a++) {
            cpa16(sp + a * GARR,      gp[a]);
            cpa16(sp + a * GARR + 16, gp[a] + 8);
        }
        cp_commit();
    }

    const int NKT = K / KT;
    for (int kt = 0; kt < NKT; kt++) {
        const int st = kt & 1;
        if (kt + 1 < NKT) {
            uint32_t base = sp + (st ^ 1) * GSTAGE;
            int k0 = (kt + 1) * KT;
#pragma unroll
            for (int a = 0; a < 4; a++) {
                cpa16(base + a * GARR,      gp[a] + k0);
                cpa16(base + a * GARR + 16, gp[a] + k0 + 8);
            }
            cp_commit();
            cp_wait1();
        } else {
            cp_wait0();
        }
        __syncthreads();

        const uint32_t stB = st * GSTAGE;
#pragma unroll
        for (int ks = 0; ks < 2; ks++) {
            const int kb = ks * 16;
            uint32_t aH[4][4], aL[4][4], bHf[2][4], bLf[2][4];
#pragma unroll
            for (int mf = 0; mf < 4; mf++) {
                uint32_t ad = aoff + stB + (mf * 16 * SSTR + kb) * 2;
                ldsm4(aH[mf], ad);
                ldsm4(aL[mf], ad + GARR);
            }
#pragma unroll
            for (int np = 0; np < 2; np++) {
                uint32_t bd = boff + stB + (np * 16 * SSTR + kb) * 2;
                ldsm4(bHf[np], bd);
                ldsm4(bLf[np], bd + GARR);
            }
            // three bf16x3 passes; dependency distance 16
#pragma unroll
            for (int mf = 0; mf < 4; mf++)
#pragma unroll
                for (int nf = 0; nf < 4; nf++)
                    mma16816(acc[mf][nf], aH[mf], &bHf[nf >> 1][(nf & 1) * 2]);
#pragma unroll
            for (int mf = 0; mf < 4; mf++)
#pragma unroll
                for (int nf = 0; nf < 4; nf++)
                    mma16816(acc[mf][nf], aH[mf], &bLf[nf >> 1][(nf & 1) * 2]);
#pragma unroll
            for (int mf = 0; mf < 4; mf++)
#pragma unroll
                for (int nf = 0; nf < 4; nf++)
                    mma16816(acc[mf][nf], aL[mf], &bHf[nf >> 1][(nf & 1) * 2]);
        }
        if (kt + 1 < NKT) __syncthreads();
    }

    // Epilogue
#pragma unroll
    for (int mf = 0; mf < 4; mf++)
#pragma unroll
        for (int nf = 0; nf < 4; nf++) {
            int r0 = m0 + wm * 64 + mf * 16 + g;
            int c0 = n0 + wn * 32 + nf * 8 + 2 * tg;
#pragma unroll
            for (int e = 0; e < 4; e++) {
                int r = r0 + ((e >= 2) ? 8 : 0);
                int c = c0 + (e & 1);
                float val = acc[mf][nf][e] + bias[c];
                if (MODE == 0) {
                    outF[(size_t)r * EMBED + c] = val;
                } else {
                    int b  = r >> 11;
                    int s  = r & (SEQ - 1);
                    int h  = c >> 6;
                    int dh = c & (HDIM - 1);
                    size_t idx;
                    if (MODE == 1)
                        idx = (((size_t)(b * HEADS + h)) * SEQ + s) * HDIM + dh;
                    else
                        idx = (((size_t)(b * HEADS + h)) * HDIM + dh) * SEQ + s;
                    __nv_bfloat16 hv = __float2bfloat16_rn(val);
                    outH[idx] = hv;
                    outL[idx] = __float2bfloat16_rn(val - __bfloat162float(hv));
                }
            }
        }
}

// ---------------------------------------------------------------------------
// Flash attention, HMMA bf16x3, cp.async double-buffered, ldmatrix-fed.
// Block = 128 queries of one (b,h); 8 warps x 16 q-rows; KV tiles of 64.
// ---------------------------------------------------------------------------
#define KSTR   72                     // halves; 144B row stride (conflict-free)
#define AARR   (64*KSTR*2)            // 9216 B per array
#define ASTAGE (4*AARR)               // 36864 B
#define ASMEM  (2*ASTAGE)             // 73728 B

__global__ __launch_bounds__(256)
void attn_mma(const __nv_bfloat16* __restrict__ qh_, const __nv_bfloat16* __restrict__ ql_,
              const __nv_bfloat16* __restrict__ kh_, const __nv_bfloat16* __restrict__ kl_,
              const __nv_bfloat16* __restrict__ vth_, const __nv_bfloat16* __restrict__ vtl_,
              const int* __restrict__ mask,
              __nv_bfloat16* __restrict__ aH, __nv_bfloat16* __restrict__ aL)
{
    extern __shared__ __nv_bfloat16 dsm[];
    const uint32_t sb = s2u(dsm);
    const int t = threadIdx.x, lane = t & 31, w = t >> 5;
    const int g = lane >> 2, tg = lane & 3;
    const int bh = blockIdx.y;
    const int q0 = blockIdx.x * 128;
    const size_t base = (size_t)bh * SEQ * HDIM;

    const int lr = t >> 2, lcb = (t & 3) * 16;
    const __nv_bfloat16* gp[4] = {
        kh_  + base + (size_t)lr * HDIM + lcb,
        kl_  + base + (size_t)lr * HDIM + lcb,
        vth_ + base + (size_t)lr * SEQ  + lcb,
        vtl_ + base + (size_t)lr * SEQ  + lcb };
    const uint32_t sp = sb + (lr * KSTR + lcb) * 2;

    const uint32_t foff = sb +
        ((((lane & 7) + (lane >> 4) * 8) * KSTR + ((lane >> 3) & 1) * 8) * 2);

    // prologue: issue tile 0
    {
#pragma unroll
        for (int a = 0; a < 4; a++) {
            cpa16(sp + a * AARR,      gp[a]);
            cpa16(sp + a * AARR + 16, gp[a] + 8);
        }
        cp_commit();
    }

    // Q fragments (loaded once, overlaps tile-0 cp.async)
    const int r0 = q0 + w * 16 + g;
    uint32_t qfh[4][4], qfl[4][4];
#pragma unroll
    for (int kf = 0; kf < 4; kf++) {
        size_t i0 = base + (size_t)r0 * HDIM + kf * 16 + 2 * tg;
        size_t i1 = base + (size_t)(r0 + 8) * HDIM + kf * 16 + 2 * tg;
        qfh[kf][0] = *(const uint32_t*)&qh_[i0];
        qfh[kf][1] = *(const uint32_t*)&qh_[i1];
        qfh[kf][2] = *(const uint32_t*)&qh_[i0 + 8];
        qfh[kf][3] = *(const uint32_t*)&qh_[i1 + 8];
        qfl[kf][0] = *(const uint32_t*)&ql_[i0];
        qfl[kf][1] = *(const uint32_t*)&ql_[i1];
        qfl[kf][2] = *(const uint32_t*)&ql_[i0 + 8];
        qfl[kf][3] = *(const uint32_t*)&ql_[i1 + 8];
    }

    float o[8][4];
#pragma unroll
    for (int nf = 0; nf < 8; nf++)
#pragma unroll
        for (int e = 0; e < 4; e++) o[nf][e] = 0.f;
    float m1 = -INFINITY, m2 = -INFINITY, l1 = 0.f, l2 = 0.f;

    const float scale = 0.125f;
    const int NIT = SEQ / 64;

    for (int it = 0; it < NIT; it++) {
        const int st = it & 1;
        if (it + 1 < NIT) {
            const int k0n = (it + 1) * 64;
            uint32_t dstb = sp + (st ^ 1) * ASTAGE;
            cpa16(dstb,               gp[0] + (size_t)k0n * HDIM);
            cpa16(dstb + 16,          gp[0] + (size_t)k0n * HDIM + 8);
            cpa16(dstb + AARR,        gp[1] + (size_t)k0n * HDIM);
            cpa16(dstb + AARR + 16,   gp[1] + (size_t)k0n * HDIM + 8);
            cpa16(dstb + 2*AARR,      gp[2] + k0n);
            cpa16(dstb + 2*AARR + 16, gp[2] + k0n + 8);
            cpa16(dstb + 3*AARR,      gp[3] + k0n);
            cpa16(dstb + 3*AARR + 16, gp[3] + k0n + 8);
            cp_commit();
            cp_wait1();
        } else {
            cp_wait0();
        }
        __syncthreads();

        const uint32_t stB = st * ASTAGE;
        const int k0 = it * 64;

        // ----- S = Q @ K^T (bf16x3) -----
        float s[8][4];
#pragma unroll
        for (int nf = 0; nf < 8; nf++)
#pragma unroll
            for (int e = 0; e < 4; e++) s[nf][e] = 0.f;

#pragma unroll
        for (int kf = 0; kf < 4; kf++) {
            uint32_t kh4[4][4], kl4[4][4];
#pragma unroll
            for (int np = 0; np < 4; np++) {
                uint32_t ad = foff + stB + (np * 16 * KSTR + kf * 16) * 2;
                ldsm4(kh4[np], ad);
                ldsm4(kl4[np], ad + AARR);
            }
#pragma unroll
            for (int nf = 0; nf < 8; nf++)
                mma16816(s[nf], qfh[kf], &kh4[nf >> 1][(nf & 1) * 2]);
#pragma unroll
            for (int nf = 0; nf < 8; nf++)
                mma16816(s[nf], qfh[kf], &kl4[nf >> 1][(nf & 1) * 2]);
#pragma unroll
            for (int nf = 0; nf < 8; nf++)
                mma16816(s[nf], qfl[kf], &kh4[nf >> 1][(nf & 1) * 2]);
        }

        // ----- scale + mask (block-skip fast path) -----
        const int mflag = g_mflag[(q0 >> 7) * (SEQ/64) + (k0 >> 6)];
        if (mflag) {
#pragma unroll
            for (int nf = 0; nf < 8; nf++) {
                int kc = k0 + nf * 8 + 2 * tg;
                int2 mv0 = *(const int2*)&mask[(size_t)r0 * SEQ + kc];
                int2 mv1 = *(const int2*)&mask[(size_t)(r0 + 8) * SEQ + kc];
                s[nf][0] = mv0.x ? s[nf][0] * scale : -1e9f;
                s[nf][1] = mv0.y ? s[nf][1] * scale : -1e9f;
                s[nf][2] = mv1.x ? s[nf][2] * scale : -1e9f;
                s[nf][3] = mv1.y ? s[nf][3] * scale : -1e9f;
            }
        } else {
#pragma unroll
            for (int nf = 0; nf < 8; nf++) {
                s[nf][0] *= scale; s[nf][1] *= scale;
                s[nf][2] *= scale; s[nf][3] *= scale;
            }
        }

        // ----- online softmax -----
        float mt1 = -INFINITY, mt2 = -INFINITY;
#pragma unroll
        for (int nf = 0; nf < 8; nf++) {
            mt1 = fmaxf(mt1, fmaxf(s[nf][0], s[nf][1]));
            mt2 = fmaxf(mt2, fmaxf(s[nf][2], s[nf][3]));
        }
        mt1 = fmaxf(mt1, __shfl_xor_sync(0xffffffffu, mt1, 1));
        mt1 = fmaxf(mt1, __shfl_xor_sync(0xffffffffu, mt1, 2));
        mt2 = fmaxf(mt2, __shfl_xor_sync(0xffffffffu, mt2, 1));
        mt2 = fmaxf(mt2, __shfl_xor_sync(0xffffffffu, mt2, 2));
        float m1n = fmaxf(m1, mt1), m2n = fmaxf(m2, mt2);
        float a1 = __expf(m1 - m1n), a2 = __expf(m2 - m2n);

        float sum1 = 0.f, sum2 = 0.f;
#pragma unroll
        for (int nf = 0; nf < 8; nf++) {
            s[nf][0] = __expf(s[nf][0] - m1n);
            s[nf][1] = __expf(s[nf][1] - m1n);
            s[nf][2] = __expf(s[nf][2] - m2n);
            s[nf][3] = __expf(s[nf][3] - m2n);
            sum1 += s[nf][0] + s[nf][1];
            sum2 += s[nf][2] + s[nf][3];
        }
        sum1 += __shfl_xor_sync(0xffffffffu, sum1, 1);
        sum1 += __shfl_xor_sync(0xffffffffu, sum1, 2);
        sum2 += __shfl_xor_sync(0xffffffffu, sum2, 1);
        sum2 += __shfl_xor_sync(0xffffffffu, sum2, 2);
        l1 = l1 * a1 + sum1;
        l2 = l2 * a2 + sum2;
        m1 = m1n; m2 = m2n;

#pragma unroll
        for (int nf = 0; nf < 8; nf++) {
            o[nf][0] *= a1; o[nf][1] *= a1;
            o[nf][2] *= a2; o[nf][3] *= a2;
        }

        // ----- O += P @ V -----
#pragma unroll
        for (int kf = 0; kf < 4; kf++) {
            uint32_t pH[4], pL[4];
            split_pack2(s[2*kf][0],   s[2*kf][1],   pH[0], pL[0]);
            split_pack2(s[2*kf][2],   s[2*kf][3],   pH[1], pL[1]);
            split_pack2(s[2*kf+1][0], s[2*kf+1][1], pH[2], pL[2]);
            split_pack2(s[2*kf+1][2], s[2*kf+1][3], pH[3], pL[3]);
            uint32_t vh4[4][4], vl4[4][4];
#pragma unroll
            for (int np = 0; np < 4; np++) {
                uint32_t ad = foff + stB + 2*AARR + (np * 16 * KSTR + kf * 16) * 2;
                ldsm4(vh4[np], ad);
                ldsm4(vl4[np], ad + AARR);
            }
#pragma unroll
            for (int nf = 0; nf < 8; nf++)
                mma16816(o[nf], pH, &vh4[nf >> 1][(nf & 1) * 2]);
#pragma unroll
            for (int nf = 0; nf < 8; nf++)
                mma16816(o[nf], pH, &vl4[nf >> 1][(nf & 1) * 2]);
#pragma unroll
            for (int nf = 0; nf < 8; nf++)
                mma16816(o[nf], pL, &vh4[nf >> 1][(nf & 1) * 2]);
        }
        if (it + 1 < NIT) __syncthreads();
    }

    // ----- epilogue -----
    const float inv1 = 1.f / l1, inv2 = 1.f / l2;
    const int b = bh / HEADS, h = bh % HEADS;
#pragma unroll
    for (int nf = 0; nf < 8; nf++) {
        int col = h * HDIM + nf * 8 + 2 * tg;
        size_t i0 = ((size_t)(b * SEQ + r0)) * EMBED + col;
        size_t i1 = ((size_t)(b * SEQ + r0 + 8)) * EMBED + col;
        float v00 = o[nf][0] * inv1, v01 = o[nf][1] * inv1;
        float v10 = o[nf][2] * inv2, v11 = o[nf][3] * inv2;
        __nv_bfloat16 hv;
        hv = __float2bfloat16_rn(v00); aH[i0]   = hv; aL[i0]   = __float2bfloat16_rn(v00 - __bfloat162float(hv));
        hv = __float2bfloat16_rn(v01); aH[i0+1] = hv; aL[i0+1] = __float2bfloat16_rn(v01 - __bfloat162float(hv));
        hv = __float2bfloat16_rn(v10); aH[i1]   = hv; aL[i1]   = __float2bfloat16_rn(v10 - __bfloat162float(hv));
        hv = __float2bfloat16_rn(v11); aH[i1+1] = hv; aL[i1+1] = __float2bfloat16_rn(v11 - __bfloat162float(hv));
    }
}

// ---------------------------------------------------------------------------
extern "C" void kernel_launch(void* const* d_in, const int* in_sizes, int n_in,
                              void* d_out, int out_size)
{
    const float* hidden = (const float*)d_in[0];
    const int*   mask   = (const int*)  d_in[1];
    const float* Wq     = (const float*)d_in[2];
    const float* bq     = (const float*)d_in[3];
    const float* Wk     = (const float*)d_in[4];
    const float* bk     = (const float*)d_in[5];
    const float* Wv     = (const float*)d_in[6];
    const float* bv     = (const float*)d_in[7];
    const float* Wo     = (const float*)d_in[8];
    const float* bo     = (const float*)d_in[9];
    float* out = (float*)d_out;

    __nv_bfloat16 *hh, *hl, *wqh, *wql, *wkh, *wkl, *wvh, *wvl, *woh, *wol;
    __nv_bfloat16 *qh, *ql, *kh, *kl, *vth, *vtl, *ah, *al;
    cudaGetSymbolAddress((void**)&hh,  g_hh);  cudaGetSymbolAddress((void**)&hl,  g_hl);
    cudaGetSymbolAddress((void**)&wqh, g_wqh); cudaGetSymbolAddress((void**)&wql, g_wql);
    cudaGetSymbolAddress((void**)&wkh, g_wkh); cudaGetSymbolAddress((void**)&wkl, g_wkl);
    cudaGetSymbolAddress((void**)&wvh, g_wvh); cudaGetSymbolAddress((void**)&wvl, g_wvl);
    cudaGetSymbolAddress((void**)&woh, g_woh); cudaGetSymbolAddress((void**)&wol, g_wol);
    cudaGetSymbolAddress((void**)&qh,  g_qh);  cudaGetSymbolAddress((void**)&ql,  g_ql);
    cudaGetSymbolAddress((void**)&kh,  g_kh);  cudaGetSymbolAddress((void**)&kl,  g_kl);
    cudaGetSymbolAddress((void**)&vth, g_vth); cudaGetSymbolAddress((void**)&vtl, g_vtl);
    cudaGetSymbolAddress((void**)&ah,  g_ah);  cudaGetSymbolAddress((void**)&al,  g_al);

    static bool attr_set = false;
    if (!attr_set) {
        cudaFuncSetAttribute(mma_gemm<0>, cudaFuncAttributeMaxDynamicSharedMemorySize, GSMEM);
        cudaFuncSetAttribute(mma_gemm<1>, cudaFuncAttributeMaxDynamicSharedMemorySize, GSMEM);
        cudaFuncSetAttribute(mma_gemm<2>, cudaFuncAttributeMaxDynamicSharedMemorySize, GSMEM);
        cudaFuncSetAttribute(attn_mma,    cudaFuncAttributeMaxDynamicSharedMemorySize, ASMEM);
        attr_set = true;
    }

    // Splits + mask flags
    const int nH = MTOT * EMBED, nW = EMBED * EMBED;
    split_kernel<<<(nH/8 + 255)/256, 256>>>(hidden, hh, hl, nH);
    split_kernel<<<(nW/8 + 255)/256, 256>>>(Wq, wqh, wql, nW);
    split_kernel<<<(nW/8 + 255)/256, 256>>>(Wk, wkh, wkl, nW);
    split_kernel<<<(nW/8 + 255)/256, 256>>>(Wv, wvh, wvl, nW);
    split_kernel<<<(nW/8 + 255)/256, 256>>>(Wo, woh, wol, nW);
    mask_flags_kernel<<<dim3(SEQ/64, SEQ/128), 256>>>(mask);

    // Projections
    dim3 gg(EMBED / 128, MTOT / 128);   // (8, 32)
    mma_gemm<1><<<gg, 256, GSMEM>>>(hh, hl, wqh, wql, bq, nullptr, qh, ql);
    mma_gemm<1><<<gg, 256, GSMEM>>>(hh, hl, wkh, wkl, bk, nullptr, kh, kl);
    mma_gemm<2><<<gg, 256, GSMEM>>>(hh, hl, wvh, wvl, bv, nullptr, vth, vtl);

    // Attention
    dim3 ag(SEQ / 128, BH);             // (16, 32)
    attn_mma<<<ag, 256, ASMEM>>>(qh, ql, kh, kl, vth, vtl, mask, ah, al);

    // Output projection
    mma_gemm<0><<<gg, 256, GSMEM>>>(ah, al, woh, wol, bo, out, nullptr, nullptr);
}

// round 8
// speedup vs baseline: 5.2623x; 1.0879x over previous
#include <cuda_runtime.h>
#include <cuda_bf16.h>
#include <math.h>
#include <stdint.h>

// Problem constants
#define BATCH 2
#define SEQ   2048
#define EMBED 1024
#define HEADS 16
#define HDIM  64
#define MTOT  (BATCH*SEQ)     // 4096
#define BH    (BATCH*HEADS)   // 32

// ---------------------------------------------------------------------------
// Scratch (device globals; no allocation allowed)
// ---------------------------------------------------------------------------
__device__ __nv_bfloat16 g_hh[MTOT*EMBED],  g_hl[MTOT*EMBED];
__device__ __nv_bfloat16 g_wqh[EMBED*EMBED], g_wql[EMBED*EMBED];
__device__ __nv_bfloat16 g_wkh[EMBED*EMBED], g_wkl[EMBED*EMBED];
__device__ __nv_bfloat16 g_wvh[EMBED*EMBED], g_wvl[EMBED*EMBED];
__device__ __nv_bfloat16 g_woh[EMBED*EMBED], g_wol[EMBED*EMBED];
__device__ __nv_bfloat16 g_qh[BH*SEQ*HDIM],  g_ql[BH*SEQ*HDIM];   // [bh][s][dh]
__device__ __nv_bfloat16 g_kh[BH*SEQ*HDIM],  g_kl[BH*SEQ*HDIM];   // [bh][s][dh]
__device__ __nv_bfloat16 g_vth[BH*SEQ*HDIM], g_vtl[BH*SEQ*HDIM];  // [bh][dh][s]
__device__ __nv_bfloat16 g_ah[MTOT*EMBED],   g_al[MTOT*EMBED];    // attn out
__device__ int g_mflag[(SEQ/128)*(SEQ/64)];                        // [16][32]

// ---------------------------------------------------------------------------
// Helpers
// ---------------------------------------------------------------------------
__device__ __forceinline__ uint32_t pack_bf2(float lo_elem, float hi_elem) {
    uint32_t r;
    asm("cvt.rn.bf16x2.f32 %0, %1, %2;" : "=r"(r) : "f"(hi_elem), "f"(lo_elem));
    return r;
}
__device__ __forceinline__ void split_pack2(float x, float y, uint32_t& hi, uint32_t& lo) {
    float xh = __bfloat162float(__float2bfloat16_rn(x));
    float yh = __bfloat162float(__float2bfloat16_rn(y));
    hi = pack_bf2(xh, yh);
    lo = pack_bf2(x - xh, y - yh);
}
__device__ __forceinline__ void mma16816(float* c, const uint32_t* a, const uint32_t* b) {
    asm volatile(
        "mma.sync.aligned.m16n8k16.row.col.f32.bf16.bf16.f32 "
        "{%0,%1,%2,%3}, {%4,%5,%6,%7}, {%8,%9}, {%0,%1,%2,%3};"
        : "+f"(c[0]), "+f"(c[1]), "+f"(c[2]), "+f"(c[3])
        : "r"(a[0]), "r"(a[1]), "r"(a[2]), "r"(a[3]), "r"(b[0]), "r"(b[1]));
}
__device__ __forceinline__ uint32_t s2u(const void* p) {
    return (uint32_t)__cvta_generic_to_shared(p);
}
__device__ __forceinline__ void cpa16(uint32_t s, const void* g) {
    asm volatile("cp.async.cg.shared.global [%0], [%1], 16;" :: "r"(s), "l"(g));
}
__device__ __forceinline__ void cp_commit() { asm volatile("cp.async.commit_group;"); }
__device__ __forceinline__ void cp_wait1() { asm volatile("cp.async.wait_group 1;"); }
__device__ __forceinline__ void cp_wait0() { asm volatile("cp.async.wait_group 0;"); }
__device__ __forceinline__ void ldsm4(uint32_t* r, uint32_t a) {
    asm volatile("ldmatrix.sync.aligned.m8n8.x4.shared.b16 {%0,%1,%2,%3}, [%4];"
        : "=r"(r[0]), "=r"(r[1]), "=r"(r[2]), "=r"(r[3]) : "r"(a));
}

// ---------------------------------------------------------------------------
// Fused split: hidden + 4 weight matrices in one launch.
// Linear element space: [0,4M) hidden, then 1M each Wq,Wk,Wv,Wo.
// ---------------------------------------------------------------------------
#define NH (MTOT*EMBED)     // 4194304
#define NW (EMBED*EMBED)    // 1048576

__global__ __launch_bounds__(256)
void split_all_kernel(const float* __restrict__ hid,
                      const float* __restrict__ Wq, const float* __restrict__ Wk,
                      const float* __restrict__ Wv, const float* __restrict__ Wo)
{
    size_t i = ((size_t)blockIdx.x * 256 + threadIdx.x) * 8;
    const float* src; __nv_bfloat16 *h, *l; size_t off;
    if (i < NH)               { src = hid; h = g_hh;  l = g_hl;  off = i; }
    else if (i < NH + NW)     { src = Wq;  h = g_wqh; l = g_wql; off = i - NH; }
    else if (i < NH + 2*NW)   { src = Wk;  h = g_wkh; l = g_wkl; off = i - NH - 2*(size_t)NW + NW; }
    else if (i < NH + 3*NW)   { src = Wv;  h = g_wvh; l = g_wvl; off = i - NH - 2*(size_t)NW; }
    else                      { src = Wo;  h = g_woh; l = g_wol; off = i - NH - 3*(size_t)NW; }
    float4 v0 = *(const float4*)(src + off);
    float4 v1 = *(const float4*)(src + off + 4);
    float a[8] = {v0.x, v0.y, v0.z, v0.w, v1.x, v1.y, v1.z, v1.w};
    uint32_t hp[4], lp[4];
#pragma unroll
    for (int j = 0; j < 4; j++) split_pack2(a[2*j], a[2*j+1], hp[j], lp[j]);
    *(uint4*)(h + off) = make_uint4(hp[0], hp[1], hp[2], hp[3]);
    *(uint4*)(l + off) = make_uint4(lp[0], lp[1], lp[2], lp[3]);
}

// ---------------------------------------------------------------------------
// Mask block flags: flag[qb][kb] = any zero in mask[qb*128.., kb*64..]
// ---------------------------------------------------------------------------
__global__ __launch_bounds__(256)
void mask_flags_kernel(const int* __restrict__ mask)
{
    const int* p = mask + (size_t)(blockIdx.y * 128) * SEQ + blockIdx.x * 64;
    int local = 0;
    for (int i = threadIdx.x; i < 128 * 16; i += 256) {
        int r = i >> 4, c4 = i & 15;
        int4 v = ((const int4*)(p + (size_t)r * SEQ))[c4];
        if (v.x == 0 || v.y == 0 || v.z == 0 || v.w == 0) local = 1;
    }
    int any = __syncthreads_or(local);
    if (threadIdx.x == 0) g_mflag[blockIdx.y * (SEQ/64) + blockIdx.x] = any;
}

// ---------------------------------------------------------------------------
// bf16x3 GEMM core: C[128,128] tile of A[M,K] @ W[N,K]^T + bias.
// KT=16, double-buffered cp.async, ldmatrix-fed, 2 CTAs/SM.
// MODE 0: fp32 row-major out. MODE 1: hi/lo bf16 head-split out
//   (trans=0: [bh][s][dh], trans=1: [bh][dh][s]).
// ---------------------------------------------------------------------------
#define KT    16
#define SSTR  24                      // halves; 48B row stride (conflict-free LDSM)
#define GARR  (128*SSTR*2)            // 6144 B per array
#define GSTAGE (4*GARR)               // 24576 B
#define GSMEM  (2*GSTAGE)             // 49152 B

template<int MODE>
__device__ __forceinline__
void gemm_body(const __nv_bfloat16* __restrict__ Ah, const __nv_bfloat16* __restrict__ Al,
               const __nv_bfloat16* __restrict__ Bh, const __nv_bfloat16* __restrict__ Bl,
               const float* __restrict__ bias,
               float* __restrict__ outF,
               __nv_bfloat16* __restrict__ outH, __nv_bfloat16* __restrict__ outL,
               int trans)
{
    extern __shared__ __nv_bfloat16 dsm[];
    const uint32_t sb = s2u(dsm);
    const int K = EMBED;
    const int t = threadIdx.x, lane = t & 31, w = t >> 5;
    const int g = lane >> 2, tg = lane & 3;
    const int wm = w >> 2, wn = w & 3;
    const int m0 = blockIdx.y * 128, n0 = blockIdx.x * 128;

    // staging: thread covers (row t>>1, halves (t&1)*8 .. +8) per array
    const int lr = t >> 1, lc = (t & 1) * 8;
    const __nv_bfloat16* gp[4] = {
        Ah + (size_t)(m0 + lr) * K + lc,
        Al + (size_t)(m0 + lr) * K + lc,
        Bh + (size_t)(n0 + lr) * K + lc,
        Bl + (size_t)(n0 + lr) * K + lc };
    const uint32_t sp = sb + (lr * SSTR + lc) * 2;

    const uint32_t aoff = sb + ((wm * 64 + (lane & 15)) * SSTR + (lane >> 4) * 8) * 2;
    const uint32_t boff = sb + 2 * GARR +
        (((wn * 32 + (lane & 7) + (lane >> 4) * 8) * SSTR + ((lane >> 3) & 1) * 8) * 2);

    float acc[4][4][4];
#pragma unroll
    for (int a = 0; a < 4; a++)
#pragma unroll
        for (int b = 0; b < 4; b++)
#pragma unroll
            for (int c = 0; c < 4; c++) acc[a][b][c] = 0.f;

    // prologue
#pragma unroll
    for (int a = 0; a < 4; a++) cpa16(sp + a * GARR, gp[a]);
    cp_commit();

    const int NKT = K / KT;   // 64
    for (int kt = 0; kt < NKT; kt++) {
        const int st = kt & 1;
        if (kt + 1 < NKT) {
            uint32_t base = sp + (st ^ 1) * GSTAGE;
            int k0 = (kt + 1) * KT;
#pragma unroll
            for (int a = 0; a < 4; a++) cpa16(base + a * GARR, gp[a] + k0);
            cp_commit();
            cp_wait1();
        } else {
            cp_wait0();
        }
        __syncthreads();

        const uint32_t stB = st * GSTAGE;
        uint32_t aH[4][4], aL[4][4], bHf[2][4], bLf[2][4];
#pragma unroll
        for (int mf = 0; mf < 4; mf++) {
            uint32_t ad = aoff + stB + (mf * 16 * SSTR) * 2;
            ldsm4(aH[mf], ad);
            ldsm4(aL[mf], ad + GARR);
        }
#pragma unroll
        for (int np = 0; np < 2; np++) {
            uint32_t bd = boff + stB + (np * 16 * SSTR) * 2;
            ldsm4(bHf[np], bd);
            ldsm4(bLf[np], bd + GARR);
        }
        // three bf16x3 passes; dependency distance 16
#pragma unroll
        for (int mf = 0; mf < 4; mf++)
#pragma unroll
            for (int nf = 0; nf < 4; nf++)
                mma16816(acc[mf][nf], aH[mf], &bHf[nf >> 1][(nf & 1) * 2]);
#pragma unroll
        for (int mf = 0; mf < 4; mf++)
#pragma unroll
            for (int nf = 0; nf < 4; nf++)
                mma16816(acc[mf][nf], aH[mf], &bLf[nf >> 1][(nf & 1) * 2]);
#pragma unroll
        for (int mf = 0; mf < 4; mf++)
#pragma unroll
            for (int nf = 0; nf < 4; nf++)
                mma16816(acc[mf][nf], aL[mf], &bHf[nf >> 1][(nf & 1) * 2]);
        if (kt + 1 < NKT) __syncthreads();
    }

    // Epilogue
#pragma unroll
    for (int mf = 0; mf < 4; mf++)
#pragma unroll
        for (int nf = 0; nf < 4; nf++) {
            int r0 = m0 + wm * 64 + mf * 16 + g;
            int c0 = n0 + wn * 32 + nf * 8 + 2 * tg;
#pragma unroll
            for (int e = 0; e < 4; e++) {
                int r = r0 + ((e >= 2) ? 8 : 0);
                int c = c0 + (e & 1);
                float val = acc[mf][nf][e] + bias[c];
                if (MODE == 0) {
                    outF[(size_t)r * EMBED + c] = val;
                } else {
                    int b  = r >> 11;
                    int s  = r & (SEQ - 1);
                    int h  = c >> 6;
                    int dh = c & (HDIM - 1);
                    size_t idx = trans
                        ? (((size_t)(b * HEADS + h)) * HDIM + dh) * SEQ + s
                        : (((size_t)(b * HEADS + h)) * SEQ + s) * HDIM + dh;
                    __nv_bfloat16 hv = __float2bfloat16_rn(val);
                    outH[idx] = hv;
                    outL[idx] = __float2bfloat16_rn(val - __bfloat162float(hv));
                }
            }
        }
}

// Fused QKV: grid.z selects projection (0=Q, 1=K, 2=V-transposed)
__global__ __launch_bounds__(256, 2)
void qkv_kernel(const __nv_bfloat16* __restrict__ hh, const __nv_bfloat16* __restrict__ hl,
                const float* __restrict__ bq, const float* __restrict__ bk,
                const float* __restrict__ bv)
{
    int z = blockIdx.z;
    if (z == 0)
        gemm_body<1>(hh, hl, g_wqh, g_wql, bq, nullptr, g_qh, g_ql, 0);
    else if (z == 1)
        gemm_body<1>(hh, hl, g_wkh, g_wkl, bk, nullptr, g_kh, g_kl, 0);
    else
        gemm_body<1>(hh, hl, g_wvh, g_wvl, bv, nullptr, g_vth, g_vtl, 1);
}

// O projection: fp32 out
__global__ __launch_bounds__(256, 2)
void oproj_kernel(const float* __restrict__ bo, float* __restrict__ out)
{
    gemm_body<0>(g_ah, g_al, g_woh, g_wol, bo, out, nullptr, nullptr, 0);
}

// ---------------------------------------------------------------------------
// Flash attention, HMMA bf16x3, cp.async double-buffered, ldmatrix-fed.
// Block = 128 queries of one (b,h); 8 warps x 16 q-rows; KV tiles of 64.
// ---------------------------------------------------------------------------
#define KSTR   72                     // halves; 144B row stride (conflict-free)
#define AARR   (64*KSTR*2)            // 9216 B per array
#define ASTAGE (4*AARR)               // 36864 B
#define ASMEM  (2*ASTAGE)             // 73728 B

__global__ __launch_bounds__(256)
void attn_mma(const __nv_bfloat16* __restrict__ qh_, const __nv_bfloat16* __restrict__ ql_,
              const __nv_bfloat16* __restrict__ kh_, const __nv_bfloat16* __restrict__ kl_,
              const __nv_bfloat16* __restrict__ vth_, const __nv_bfloat16* __restrict__ vtl_,
              const int* __restrict__ mask,
              __nv_bfloat16* __restrict__ aH, __nv_bfloat16* __restrict__ aL)
{
    extern __shared__ __nv_bfloat16 dsm[];
    const uint32_t sb = s2u(dsm);
    const int t = threadIdx.x, lane = t & 31, w = t >> 5;
    const int g = lane >> 2, tg = lane & 3;
    const int bh = blockIdx.y;
    const int q0 = blockIdx.x * 128;
    const size_t base = (size_t)bh * SEQ * HDIM;

    const int lr = t >> 2, lcb = (t & 3) * 16;
    const __nv_bfloat16* gp[4] = {
        kh_  + base + (size_t)lr * HDIM + lcb,
        kl_  + base + (size_t)lr * HDIM + lcb,
        vth_ + base + (size_t)lr * SEQ  + lcb,
        vtl_ + base + (size_t)lr * SEQ  + lcb };
    const uint32_t sp = sb + (lr * KSTR + lcb) * 2;

    const uint32_t foff = sb +
        ((((lane & 7) + (lane >> 4) * 8) * KSTR + ((lane >> 3) & 1) * 8) * 2);

    // prologue: issue tile 0
    {
#pragma unroll
        for (int a = 0; a < 4; a++) {
            cpa16(sp + a * AARR,      gp[a]);
            cpa16(sp + a * AARR + 16, gp[a] + 8);
        }
        cp_commit();
    }

    // Q fragments (loaded once, overlaps tile-0 cp.async)
    const int r0 = q0 + w * 16 + g;
    uint32_t qfh[4][4], qfl[4][4];
#pragma unroll
    for (int kf = 0; kf < 4; kf++) {
        size_t i0 = base + (size_t)r0 * HDIM + kf * 16 + 2 * tg;
        size_t i1 = base + (size_t)(r0 + 8) * HDIM + kf * 16 + 2 * tg;
        qfh[kf][0] = *(const uint32_t*)&qh_[i0];
        qfh[kf][1] = *(const uint32_t*)&qh_[i1];
        qfh[kf][2] = *(const uint32_t*)&qh_[i0 + 8];
        qfh[kf][3] = *(const uint32_t*)&qh_[i1 + 8];
        qfl[kf][0] = *(const uint32_t*)&ql_[i0];
        qfl[kf][1] = *(const uint32_t*)&ql_[i1];
        qfl[kf][2] = *(const uint32_t*)&ql_[i0 + 8];
        qfl[kf][3] = *(const uint32_t*)&ql_[i1 + 8];
    }

    float o[8][4];
#pragma unroll
    for (int nf = 0; nf < 8; nf++)
#pragma unroll
        for (int e = 0; e < 4; e++) o[nf][e] = 0.f;
    float m1 = -INFINITY, m2 = -INFINITY, l1 = 0.f, l2 = 0.f;

    const float scale = 0.125f;
    const int NIT = SEQ / 64;

    for (int it = 0; it < NIT; it++) {
        const int st = it & 1;
        if (it + 1 < NIT) {
            const int k0n = (it + 1) * 64;
            uint32_t dstb = sp + (st ^ 1) * ASTAGE;
            cpa16(dstb,               gp[0] + (size_t)k0n * HDIM);
            cpa16(dstb + 16,          gp[0] + (size_t)k0n * HDIM + 8);
            cpa16(dstb + AARR,        gp[1] + (size_t)k0n * HDIM);
            cpa16(dstb + AARR + 16,   gp[1] + (size_t)k0n * HDIM + 8);
            cpa16(dstb + 2*AARR,      gp[2] + k0n);
            cpa16(dstb + 2*AARR + 16, gp[2] + k0n + 8);
            cpa16(dstb + 3*AARR,      gp[3] + k0n);
            cpa16(dstb + 3*AARR + 16, gp[3] + k0n + 8);
            cp_commit();
            cp_wait1();
        } else {
            cp_wait0();
        }
        __syncthreads();

        const uint32_t stB = st * ASTAGE;
        const int k0 = it * 64;

        // ----- S = Q @ K^T (bf16x3) -----
        float s[8][4];
#pragma unroll
        for (int nf = 0; nf < 8; nf++)
#pragma unroll
            for (int e = 0; e < 4; e++) s[nf][e] = 0.f;

#pragma unroll
        for (int kf = 0; kf < 4; kf++) {
            uint32_t kh4[4][4], kl4[4][4];
#pragma unroll
            for (int np = 0; np < 4; np++) {
                uint32_t ad = foff + stB + (np * 16 * KSTR + kf * 16) * 2;
                ldsm4(kh4[np], ad);
                ldsm4(kl4[np], ad + AARR);
            }
#pragma unroll
            for (int nf = 0; nf < 8; nf++)
                mma16816(s[nf], qfh[kf], &kh4[nf >> 1][(nf & 1) * 2]);
#pragma unroll
            for (int nf = 0; nf < 8; nf++)
                mma16816(s[nf], qfh[kf], &kl4[nf >> 1][(nf & 1) * 2]);
#pragma unroll
            for (int nf = 0; nf < 8; nf++)
                mma16816(s[nf], qfl[kf], &kh4[nf >> 1][(nf & 1) * 2]);
        }

        // ----- scale + mask (block-skip fast path) -----
        const int mflag = g_mflag[(q0 >> 7) * (SEQ/64) + (k0 >> 6)];
        if (mflag) {
#pragma unroll
            for (int nf = 0; nf < 8; nf++) {
                int kc = k0 + nf * 8 + 2 * tg;
                int2 mv0 = *(const int2*)&mask[(size_t)r0 * SEQ + kc];
                int2 mv1 = *(const int2*)&mask[(size_t)(r0 + 8) * SEQ + kc];
                s[nf][0] = mv0.x ? s[nf][0] * scale : -1e9f;
                s[nf][1] = mv0.y ? s[nf][1] * scale : -1e9f;
                s[nf][2] = mv1.x ? s[nf][2] * scale : -1e9f;
                s[nf][3] = mv1.y ? s[nf][3] * scale : -1e9f;
            }
        } else {
#pragma unroll
            for (int nf = 0; nf < 8; nf++) {
                s[nf][0] *= scale; s[nf][1] *= scale;
                s[nf][2] *= scale; s[nf][3] *= scale;
            }
        }

        // ----- online softmax -----
        float mt1 = -INFINITY, mt2 = -INFINITY;
#pragma unroll
        for (int nf = 0; nf < 8; nf++) {
            mt1 = fmaxf(mt1, fmaxf(s[nf][0], s[nf][1]));
            mt2 = fmaxf(mt2, fmaxf(s[nf][2], s[nf][3]));
        }
        mt1 = fmaxf(mt1, __shfl_xor_sync(0xffffffffu, mt1, 1));
        mt1 = fmaxf(mt1, __shfl_xor_sync(0xffffffffu, mt1, 2));
        mt2 = fmaxf(mt2, __shfl_xor_sync(0xffffffffu, mt2, 1));
        mt2 = fmaxf(mt2, __shfl_xor_sync(0xffffffffu, mt2, 2));
        float m1n = fmaxf(m1, mt1), m2n = fmaxf(m2, mt2);
        float a1 = __expf(m1 - m1n), a2 = __expf(m2 - m2n);

        float sum1 = 0.f, sum2 = 0.f;
#pragma unroll
        for (int nf = 0; nf < 8; nf++) {
            s[nf][0] = __expf(s[nf][0] - m1n);
            s[nf][1] = __expf(s[nf][1] - m1n);
            s[nf][2] = __expf(s[nf][2] - m2n);
            s[nf][3] = __expf(s[nf][3] - m2n);
            sum1 += s[nf][0] + s[nf][1];
            sum2 += s[nf][2] + s[nf][3];
        }
        sum1 += __shfl_xor_sync(0xffffffffu, sum1, 1);
        sum1 += __shfl_xor_sync(0xffffffffu, sum1, 2);
        sum2 += __shfl_xor_sync(0xffffffffu, sum2, 1);
        sum2 += __shfl_xor_sync(0xffffffffu, sum2, 2);
        l1 = l1 * a1 + sum1;
        l2 = l2 * a2 + sum2;
        m1 = m1n; m2 = m2n;

#pragma unroll
        for (int nf = 0; nf < 8; nf++) {
            o[nf][0] *= a1; o[nf][1] *= a1;
            o[nf][2] *= a2; o[nf][3] *= a2;
        }

        // ----- O += P @ V -----
#pragma unroll
        for (int kf = 0; kf < 4; kf++) {
            uint32_t pH[4], pL[4];
            split_pack2(s[2*kf][0],   s[2*kf][1],   pH[0], pL[0]);
            split_pack2(s[2*kf][2],   s[2*kf][3],   pH[1], pL[1]);
            split_pack2(s[2*kf+1][0], s[2*kf+1][1], pH[2], pL[2]);
            split_pack2(s[2*kf+1][2], s[2*kf+1][3], pH[3], pL[3]);
            uint32_t vh4[4][4], vl4[4][4];
#pragma unroll
            for (int np = 0; np < 4; np++) {
                uint32_t ad = foff + stB + 2*AARR + (np * 16 * KSTR + kf * 16) * 2;
                ldsm4(vh4[np], ad);
                ldsm4(vl4[np], ad + AARR);
            }
#pragma unroll
            for (int nf = 0; nf < 8; nf++)
                mma16816(o[nf], pH, &vh4[nf >> 1][(nf & 1) * 2]);
#pragma unroll
            for (int nf = 0; nf < 8; nf++)
                mma16816(o[nf], pH, &vl4[nf >> 1][(nf & 1) * 2]);
#pragma unroll
            for (int nf = 0; nf < 8; nf++)
                mma16816(o[nf], pL, &vh4[nf >> 1][(nf & 1) * 2]);
        }
        if (it + 1 < NIT) __syncthreads();
    }

    // ----- epilogue -----
    const float inv1 = 1.f / l1, inv2 = 1.f / l2;
    const int b = bh / HEADS, h = bh % HEADS;
#pragma unroll
    for (int nf = 0; nf < 8; nf++) {
        int col = h * HDIM + nf * 8 + 2 * tg;
        size_t i0 = ((size_t)(b * SEQ + r0)) * EMBED + col;
        size_t i1 = ((size_t)(b * SEQ + r0 + 8)) * EMBED + col;
        float v00 = o[nf][0] * inv1, v01 = o[nf][1] * inv1;
        float v10 = o[nf][2] * inv2, v11 = o[nf][3] * inv2;
        __nv_bfloat16 hv;
        hv = __float2bfloat16_rn(v00); aH[i0]   = hv; aL[i0]   = __float2bfloat16_rn(v00 - __bfloat162float(hv));
        hv = __float2bfloat16_rn(v01); aH[i0+1] = hv; aL[i0+1] = __float2bfloat16_rn(v01 - __bfloat162float(hv));
        hv = __float2bfloat16_rn(v10); aH[i1]   = hv; aL[i1]   = __float2bfloat16_rn(v10 - __bfloat162float(hv));
        hv = __float2bfloat16_rn(v11); aH[i1+1] = hv; aL[i1+1] = __float2bfloat16_rn(v11 - __bfloat162float(hv));
    }
}

// ---------------------------------------------------------------------------
extern "C" void kernel_launch(void* const* d_in, const int* in_sizes, int n_in,
                              void* d_out, int out_size)
{
    const float* hidden = (const float*)d_in[0];
    const int*   mask   = (const int*)  d_in[1];
    const float* Wq     = (const float*)d_in[2];
    const float* bq     = (const float*)d_in[3];
    const float* Wk     = (const float*)d_in[4];
    const float* bk     = (const float*)d_in[5];
    const float* Wv     = (const float*)d_in[6];
    const float* bv     = (const float*)d_in[7];
    const float* Wo     = (const float*)d_in[8];
    const float* bo     = (const float*)d_in[9];
    float* out = (float*)d_out;

    __nv_bfloat16 *hh, *hl, *qh, *ql, *kh, *kl, *vth, *vtl, *ah, *al;
    cudaGetSymbolAddress((void**)&hh,  g_hh);  cudaGetSymbolAddress((void**)&hl,  g_hl);
    cudaGetSymbolAddress((void**)&qh,  g_qh);  cudaGetSymbolAddress((void**)&ql,  g_ql);
    cudaGetSymbolAddress((void**)&kh,  g_kh);  cudaGetSymbolAddress((void**)&kl,  g_kl);
    cudaGetSymbolAddress((void**)&vth, g_vth); cudaGetSymbolAddress((void**)&vtl, g_vtl);
    cudaGetSymbolAddress((void**)&ah,  g_ah);  cudaGetSymbolAddress((void**)&al,  g_al);

    static bool attr_set = false;
    if (!attr_set) {
        cudaFuncSetAttribute(qkv_kernel,   cudaFuncAttributeMaxDynamicSharedMemorySize, GSMEM);
        cudaFuncSetAttribute(oproj_kernel, cudaFuncAttributeMaxDynamicSharedMemorySize, GSMEM);
        cudaFuncSetAttribute(attn_mma,     cudaFuncAttributeMaxDynamicSharedMemorySize, ASMEM);
        attr_set = true;
    }

    // Fused splits + mask flags
    const size_t nTot = (size_t)NH + 4 * (size_t)NW;   // 8388608
    split_all_kernel<<<(unsigned)(nTot / 8 / 256), 256>>>(hidden, Wq, Wk, Wv, Wo);
    mask_flags_kernel<<<dim3(SEQ/64, SEQ/128), 256>>>(mask);

    // Fused QKV projections (grid.z = 3)
    dim3 gq(EMBED / 128, MTOT / 128, 3);   // (8, 32, 3) = 768 CTAs
    qkv_kernel<<<gq, 256, GSMEM>>>(hh, hl, bq, bk, bv);

    // Attention
    dim3 ag(SEQ / 128, BH);                // (16, 32)
    attn_mma<<<ag, 256, ASMEM>>>(qh, ql, kh, kl, vth, vtl, mask, ah, al);

    // Output projection (single wave at 2 CTAs/SM)
    dim3 go(EMBED / 128, MTOT / 128);      // (8, 32)
    oproj_kernel<<<go, 256, GSMEM>>>(bo, out);
}